// round 1
// baseline (speedup 1.0000x reference)
#include <cuda_runtime.h>
#include <math.h>

// Problem constants
#define WE    300      // word-embedding dim
#define RVLD  320      // padded row length for rvT (1280B, 128-aligned)
#define DE    256      // doc-embedding dim
#define NV    50000    // vocab
#define ND    100000   // docs
#define NB    4096     // batch
#define NGW   10       // words per bag
#define NZ    10       // negatives
#define KP    320      // padded K for GEMM (300 -> 320, zero fill)

#define BM 64
#define BN 64
#define BK 32

// ---- device scratch (static allocation; no runtime mallocs) ----
__device__ float  d_rvT[NV * RVLD];        // 64 MB   rv transposed (v-major rows)
__device__ float  d_rdT[ND * DE];          // 102 MB  rd transposed (doc-major rows)
__device__ float  d_normedT[NB * KP];      // 5 MB    normalized g, (b, we) rows, zero-padded
__device__ float  d_projP[DE * KP];        // 0.3 MB  proj padded to KP
__device__ float  d_tpreT[NB * DE];        // 4 MB    t_pre transposed (b, de)
__device__ double d_sum[DE];
__device__ double d_sumsq[DE];
__device__ double d_rdsq;
__device__ double d_projsq;
__device__ double d_loss;
__device__ float  d_ca[DE];                // 1/sqrt(std)
__device__ float  d_cb[DE];                // beta - mean/sqrt(std)

__device__ __forceinline__ float warp_sum(float v) {
    #pragma unroll
    for (int o = 16; o > 0; o >>= 1) v += __shfl_xor_sync(0xffffffffu, v, o);
    return v;
}

// ---- K0: zero accumulators ----
__global__ void k_init() {
    int t = threadIdx.x;
    if (t < DE) { d_sum[t] = 0.0; d_sumsq[t] = 0.0; }
    if (t == 256) d_rdsq = 0.0;
    if (t == 257) d_projsq = 0.0;
    if (t == 258) d_loss = 0.0;
}

// ---- K1: transpose rd (256 x 100000) -> rdT (100000 x 256), fused sum(rd^2) ----
__global__ __launch_bounds__(256) void k_rd_T(const float* __restrict__ rd) {
    __shared__ float tile[32][33];
    int tx = threadIdx.x, ty = threadIdx.y;
    int x  = blockIdx.x * 32 + tx;    // doc
    int y0 = blockIdx.y * 32;         // de
    float ss = 0.f;
    #pragma unroll
    for (int i = 0; i < 32; i += 8) {
        float v = rd[(y0 + ty + i) * ND + x];
        tile[ty + i][tx] = v;
        ss += v * v;
    }
    __syncthreads();
    int xo = y0 + tx;                 // de
    int yo = blockIdx.x * 32;         // doc
    #pragma unroll
    for (int i = 0; i < 32; i += 8)
        d_rdT[(yo + ty + i) * DE + xo] = tile[tx][ty + i];

    ss = warp_sum(ss);
    __shared__ float red[8];
    int tid = ty * 32 + tx;
    if ((tid & 31) == 0) red[tid >> 5] = ss;
    __syncthreads();
    if (tid == 0) {
        float s = 0.f;
        #pragma unroll
        for (int i = 0; i < 8; i++) s += red[i];
        atomicAdd(&d_rdsq, (double)s);
    }
}

// ---- K2: transpose rv (300 x 50000) -> rvT (50000 x 320-padded) ----
__global__ __launch_bounds__(256) void k_rv_T(const float* __restrict__ rv) {
    __shared__ float tile[32][33];
    int tx = threadIdx.x, ty = threadIdx.y;
    int x  = blockIdx.x * 32 + tx;    // v
    int y0 = blockIdx.y * 32;         // we
    #pragma unroll
    for (int i = 0; i < 32; i += 8) {
        int y = y0 + ty + i;
        tile[ty + i][tx] = (y < WE && x < NV) ? rv[y * NV + x] : 0.f;
    }
    __syncthreads();
    int xo = y0 + tx;                 // we
    int y1 = blockIdx.x * 32;         // v
    #pragma unroll
    for (int i = 0; i < 32; i += 8) {
        int y = y1 + ty + i;
        if (y < NV && xo < WE) d_rvT[y * RVLD + xo] = tile[tx][ty + i];
    }
}

// ---- K3: pad proj into projP, fused sum(proj^2) ----
__global__ __launch_bounds__(RVLD) void k_proj_prep(const float* __restrict__ proj) {
    int de = blockIdx.x, t = threadIdx.x;
    float v = (t < WE) ? proj[de * WE + t] : 0.f;
    d_projP[de * KP + t] = v;
    float ss = warp_sum(v * v);
    __shared__ float red[10];
    if ((t & 31) == 0) red[t >> 5] = ss;
    __syncthreads();
    if (t == 0) {
        float s = 0.f;
        #pragma unroll
        for (int i = 0; i < 10; i++) s += red[i];
        atomicAdd(&d_projsq, (double)s);
    }
}

// ---- K4: gather 10 rvT rows per b, sum, L2-normalize (mean /10 cancels) ----
__global__ __launch_bounds__(RVLD) void k_gather(const int* __restrict__ word_ids) {
    int b = blockIdx.x, t = threadIdx.x;
    __shared__ int ids[NGW];
    if (t < NGW) ids[t] = word_ids[b * NGW + t];
    __syncthreads();
    float s = 0.f;
    if (t < WE) {
        #pragma unroll
        for (int g = 0; g < NGW; g++) s += d_rvT[ids[g] * RVLD + t];
    }
    float ss = warp_sum(s * s);
    __shared__ float red[10];
    __shared__ float rn;
    if ((t & 31) == 0) red[t >> 5] = ss;
    __syncthreads();
    if (t == 0) {
        float q = 0.f;
        #pragma unroll
        for (int i = 0; i < 10; i++) q += red[i];
        rn = 1.f / sqrtf(q);
    }
    __syncthreads();
    d_normedT[b * KP + t] = (t < WE) ? s * rn : 0.f;
}

// ---- K5: t_preT[b,de] = sum_we normedT[b,we]*projP[de,we]; fused row Σ/Σ² ----
__global__ __launch_bounds__(256) void k_gemm() {
    __shared__ float As[BM][BK + 1];
    __shared__ float Bs[BN][BK + 1];
    int tid = threadIdx.x;
    int tx = tid & 15, ty = tid >> 4;
    int b0 = blockIdx.x * BM;
    int d0 = blockIdx.y * BN;
    float acc[4][4];
    #pragma unroll
    for (int i = 0; i < 4; i++)
        #pragma unroll
        for (int j = 0; j < 4; j++) acc[i][j] = 0.f;

    for (int k0 = 0; k0 < KP; k0 += BK) {
        #pragma unroll
        for (int l = 0; l < 2; l++) {
            int f = tid + l * 256;
            int r = f >> 3, c = (f & 7) << 2;
            float4 va = *(const float4*)&d_normedT[(b0 + r) * KP + k0 + c];
            As[r][c] = va.x; As[r][c+1] = va.y; As[r][c+2] = va.z; As[r][c+3] = va.w;
            float4 vb = *(const float4*)&d_projP[(d0 + r) * KP + k0 + c];
            Bs[r][c] = vb.x; Bs[r][c+1] = vb.y; Bs[r][c+2] = vb.z; Bs[r][c+3] = vb.w;
        }
        __syncthreads();
        #pragma unroll
        for (int k = 0; k < BK; k++) {
            float a[4], bb[4];
            #pragma unroll
            for (int i = 0; i < 4; i++) a[i] = As[ty * 4 + i][k];
            #pragma unroll
            for (int j = 0; j < 4; j++) bb[j] = Bs[tx * 4 + j][k];
            #pragma unroll
            for (int i = 0; i < 4; i++)
                #pragma unroll
                for (int j = 0; j < 4; j++) acc[i][j] += a[i] * bb[j];
        }
        __syncthreads();
    }

    #pragma unroll
    for (int i = 0; i < 4; i++) {
        float4 o = make_float4(acc[i][0], acc[i][1], acc[i][2], acc[i][3]);
        *(float4*)&d_tpreT[(b0 + ty * 4 + i) * DE + d0 + tx * 4] = o;
    }

    __shared__ float stS[16][64];
    __shared__ float stQ[16][64];
    #pragma unroll
    for (int j = 0; j < 4; j++) {
        float s = 0.f, q = 0.f;
        #pragma unroll
        for (int i = 0; i < 4; i++) { s += acc[i][j]; q += acc[i][j] * acc[i][j]; }
        stS[ty][tx * 4 + j] = s;
        stQ[ty][tx * 4 + j] = q;
    }
    __syncthreads();
    if (tid < 64) {
        float s = 0.f, q = 0.f;
        #pragma unroll
        for (int r = 0; r < 16; r++) { s += stS[r][tid]; q += stQ[r][tid]; }
        atomicAdd(&d_sum[d0 + tid], (double)s);
        atomicAdd(&d_sumsq[d0 + tid], (double)q);
    }
}

// ---- K6: finalize per-de affine: t = clip(t_pre * ca + cb) ----
__global__ void k_stats(const float* __restrict__ beta) {
    int de = threadIdx.x;
    double s = d_sum[de], q = d_sumsq[de];
    double mean = s / NB;
    double var = (q - s * mean) / (NB - 1);   // ddof = 1
    if (var < 1e-30) var = 1e-30;
    double rs = 1.0 / sqrt(sqrt(var));        // 1 / sqrt(std), std = sqrt(var)
    d_ca[de] = (float)rs;
    d_cb[de] = (float)((double)beta[de] - mean * rs);
}

// ---- K7: per-b loss: 11 coalesced dot products from rdT + sigmoid/log ----
__global__ __launch_bounds__(256) void k_loss(const int* __restrict__ doc_ids,
                                              const int* __restrict__ neg_ids) {
    int b = blockIdx.x, tid = threadIdx.x;
    int w = tid >> 5, lane = tid & 31;
    __shared__ int   nid[NZ];
    __shared__ int   did;
    __shared__ float part[1 + NZ][8];
    if (tid == 0) did = doc_ids[b];
    if (tid < NZ) nid[tid] = neg_ids[b * NZ + tid];

    float t = d_tpreT[b * DE + tid] * d_ca[tid] + d_cb[tid];
    t = fminf(1.f, fmaxf(-1.f, t));
    __syncthreads();

    {
        float v = warp_sum(t * d_rdT[did * DE + tid]);
        if (!lane) part[0][w] = v;
    }
    #pragma unroll
    for (int z = 0; z < NZ; z++) {
        float v = warp_sum(t * d_rdT[nid[z] * DE + tid]);
        if (!lane) part[1 + z][w] = v;
    }
    __syncthreads();
    if (tid == 0) {
        float sp = 0.f;
        #pragma unroll
        for (int i = 0; i < 8; i++) sp += part[0][i];
        float p  = fminf(1.f / (1.f + expf(-sp)), 0.999f);
        float lp = 10.f * logf(p);
        float nsl = 0.f;
        #pragma unroll
        for (int z = 0; z < NZ; z++) {
            float sn = 0.f;
            #pragma unroll
            for (int i = 0; i < 8; i++) sn += part[1 + z][i];
            float pn = fminf(1.f / (1.f + expf(-sn)), 0.999f);
            nsl += logf(fmaxf(1.f - pn, 0.01f));
        }
        atomicAdd(&d_loss, (double)(0.55f * (lp + nsl)));   // (Z+1)/(2Z) = 0.55
    }
}

// ---- K8: final scalar ----
__global__ void k_final(float* __restrict__ out) {
    out[0] = (float)(d_loss / NB + (0.01 / (2.0 * NB)) * (d_rdsq + d_projsq));
}

extern "C" void kernel_launch(void* const* d_in, const int* in_sizes, int n_in,
                              void* d_out, int out_size) {
    const float* rv       = (const float*)d_in[0];
    const float* rd       = (const float*)d_in[1];
    const float* proj     = (const float*)d_in[2];
    const float* beta     = (const float*)d_in[3];
    const int*   word_ids = (const int*)d_in[4];
    const int*   doc_ids  = (const int*)d_in[5];
    const int*   neg_ids  = (const int*)d_in[6];
    float* out = (float*)d_out;

    k_init<<<1, 512>>>();
    k_rd_T<<<dim3(ND / 32, DE / 32), dim3(32, 8)>>>(rd);
    k_proj_prep<<<DE, RVLD>>>(proj);
    // rv transpose immediately before the gather so rvT is L2-hot
    k_rv_T<<<dim3((NV + 31) / 32, (WE + 31) / 32), dim3(32, 8)>>>(rv);
    k_gather<<<NB, RVLD>>>(word_ids);
    k_gemm<<<dim3(NB / BM, DE / BN), 256>>>();
    k_stats<<<1, DE>>>(beta);
    k_loss<<<NB, DE>>>(doc_ids, neg_ids);
    k_final<<<1, 1>>>(out);
}